// round 10
// baseline (speedup 1.0000x reference)
#include <cuda_runtime.h>
#include <cuda_bf16.h>

#define BB 8
#define FF 128
#define PP 256
#define TT 2048

__device__ __forceinline__ float ex2f(float x) {
    float r;
    asm("ex2.approx.f32 %0, %1;" : "=f"(r) : "f"(x));
    return r;
}

// warp-autonomous: warp owns 32 ticks x 32 pe-channels. No smem, no barriers.
// Inner loop: ex2-form weights + software pipelining (next flash's shfls issue
// before current flash's FMA block, hiding SHFL latency under FFMA issue).
__global__ __launch_bounds__(128, 7)
void flash_reco_kernel(const float* __restrict__ pe,     // [B,F,P]
                       const float* __restrict__ ftime,  // [B,F]
                       const float* __restrict__ conf,   // [B,F]
                       const float* __restrict__ sigma_ptr,
                       float* __restrict__ out)          // [B,P,T]
{
    const int lane = threadIdx.x & 31;
    const int warp = threadIdx.x >> 5;
    const int b    = blockIdx.z;
    const int p0   = blockIdx.y * 32;
    const int t0   = blockIdx.x * 128 + warp * 32;

    const float* __restrict__ base = pe + (size_t)(b * FF) * PP + p0;

    // cooperative prefetch: warm all 128 pe rows at this p0 (overlaps prefix RT)
    asm volatile("prefetch.global.L1 [%0];"
                 :: "l"(base + (warp * 32 + lane) * PP));

    const float sigma = sigma_ptr ? __ldg(sigma_ptr) : 1.0f;
    const float inv_s = 1.0f / sigma;
    const float W     = 7.0f * sigma;             // exp(-24.5) ~ 2e-11: negligible
    // interior normalizer: sigma*sqrt(2*pi); theta correction < 2.7e-9 @ sigma>=0.9
    const float inv_anorm = 1.0f / (sigma * 2.5066282746310002f + 1e-10f);
    const bool  analytic_ok = (sigma >= 0.9f);
    const float c2 = -0.72134752044448170f * inv_s * inv_s;  // -log2(e)/2 / s^2

    // ---- prefix: lane owns f = 4*lane+j; precompute tb and lc=log2(cs) ----
    float4 tb4 = __ldg(reinterpret_cast<const float4*>(ftime + b * FF) + lane);
    float4 cf4 = __ldg(reinterpret_cast<const float4*>(conf  + b * FF) + lane);
    float tbs[4], lcs[4];
    tbs[0] = fminf(fmaxf(tb4.x * (float)TT, 0.0f), (float)(TT - 1));
    tbs[1] = fminf(fmaxf(tb4.y * (float)TT, 0.0f), (float)(TT - 1));
    tbs[2] = fminf(fmaxf(tb4.z * (float)TT, 0.0f), (float)(TT - 1));
    tbs[3] = fminf(fmaxf(tb4.w * (float)TT, 0.0f), (float)(TT - 1));
    lcs[0] = __log2f(cf4.x * inv_anorm);          // conf>=0: log2(0)=-inf -> w=0 ok
    lcs[1] = __log2f(cf4.y * inv_anorm);
    lcs[2] = __log2f(cf4.z * inv_anorm);
    lcs[3] = __log2f(cf4.w * inv_anorm);

    const float t_f = (float)(t0 + lane);
    const float wlo = (float)t0 - W;
    const float whi = (float)(t0 + 31) + W;
    const float elo = W, ehi = (float)(TT - 1) - W;

    unsigned long long acc[16];                   // 16 packed f32x2 = 32 p's
    #pragma unroll
    for (int j = 0; j < 16; ++j) acc[j] = 0ull;

    #pragma unroll
    for (int j = 0; j < 4; ++j) {
        unsigned mask =
            __ballot_sync(0xffffffffu, tbs[j] >= wlo && tbs[j] <= whi);
        if (!mask) continue;                      // warp-uniform

        // pipeline prologue: fetch flash 0's broadcast state
        int k = __ffs(mask) - 1;  mask &= mask - 1;
        float tbc = __shfl_sync(0xffffffffu, tbs[j], k);
        float lcc = __shfl_sync(0xffffffffu, lcs[j], k);
        const ulonglong2* rowc =
            reinterpret_cast<const ulonglong2*>(base + (4 * k + j) * PP);
        int kc = k;

        for (;;) {
            // ---- issue NEXT flash's shfls early (overlap with FMA block) ----
            const bool more = (mask != 0);        // warp-uniform
            int kn = more ? (__ffs(mask) - 1) : kc;
            if (more) mask &= mask - 1;
            float tbn = __shfl_sync(0xffffffffu, tbs[j], kn);
            float lcn = __shfl_sync(0xffffffffu, lcs[j], kn);
            const ulonglong2* rown =
                reinterpret_cast<const ulonglong2*>(base + (4 * kn + j) * PP);

            // ---- current flash ----
            float lc = lcc;
            if (!(analytic_ok && tbc >= elo && tbc <= ehi)) {  // rare, uniform
                const int lo = max(0, (int)ceilf(tbc - W));
                const int hi = min(TT - 1, (int)floorf(tbc + W));
                float s = 0.0f;
                for (int t = lo + lane; t <= hi; t += 32) {
                    const float zz = ((float)t - tbc) * inv_s;
                    s += __expf(-0.5f * zz * zz);
                }
                #pragma unroll
                for (int d = 16; d > 0; d >>= 1)
                    s += __shfl_xor_sync(0xffffffffu, s, d);
                const float cfk = __ldg(&conf[b * FF + 4 * kc + j]);
                lc = __log2f(cfk / (s + 1e-10f));
            }

            const float u = t_f - tbc;
            const float w = ex2f(fmaf(u * c2, u, lc));
            unsigned long long ww;
            asm("mov.b64 %0, {%1, %1};" : "=l"(ww) : "f"(w));

            #pragma unroll
            for (int q = 0; q < 8; ++q) {
                ulonglong2 v = __ldg(&rowc[q]);   // uniform broadcast, L1-warm
                asm("fma.rn.f32x2 %0, %1, %2, %0;"
                    : "+l"(acc[2 * q])     : "l"(ww), "l"(v.x));
                asm("fma.rn.f32x2 %0, %1, %2, %0;"
                    : "+l"(acc[2 * q + 1]) : "l"(ww), "l"(v.y));
            }

            if (!more) break;
            tbc = tbn; lcc = lcn; rowc = rown; kc = kn;   // rotate pipeline
        }
    }

    // ---- stores: lanes span contiguous t -> coalesced 128B warp stores ----
    float* op = out + (size_t)(b * PP + p0) * TT + t0 + lane;
    #pragma unroll
    for (int j = 0; j < 16; ++j) {
        float lo, hi;
        asm("mov.b64 {%0, %1}, %2;" : "=f"(lo), "=f"(hi) : "l"(acc[j]));
        op[(size_t)(2 * j)     * TT] = lo;
        op[(size_t)(2 * j + 1) * TT] = hi;
    }
}

extern "C" void kernel_launch(void* const* d_in, const int* in_sizes, int n_in,
                              void* d_out, int out_size)
{
    const float* pe = (const float*)d_in[0];           // flashes_pe [B,F,P]
    const float* tm = (const float*)d_in[1];           // flashes_time [B,F,1]
    const float* cf = (const float*)d_in[2];           // flashes_confidence [B,F,1]
    const float* sg = (n_in >= 4) ? (const float*)d_in[n_in - 1] : nullptr;  // sigma last

    dim3 grid(TT / 128, PP / 32, BB);                  // 16 x 8 x 8 = 1024 blocks
    flash_reco_kernel<<<grid, 128>>>(pe, tm, cf, sg, (float*)d_out);
}